// round 9
// baseline (speedup 1.0000x reference)
#include <cuda_runtime.h>
#include <cuda_bf16.h>
#include <cstdint>

// ============================================================================
// drug[32768,4,512] f32, Wk/Wq/Wv[512,64] f32 -> out[32768,64] f32
// out[b] = max_n softmax_m( (X Wk)(X Wq)^T )[n,:] @ (X Wv),  X = drug[b] (4x512)
//
// 32 batches/CTA -> GEMM [128x512]@[512x192] via mma.sync.m16n8k8 TF32.
// R9: 384 threads (12 warps, 4x3, warp tile 32x64) for 168-reg budget;
// explicit kk-level fragment double-buffering so LDS latency hides under the
// MMA stream. Fragment-order smem layouts (B pre-permuted in prepass).
// ============================================================================

namespace {
constexpr int F        = 512;
constexpr int KT       = 64;
constexpr int NSLICES  = F / KT;      // 8
constexpr int THREADS  = 384;         // 12 warps, 4 row x 3 col groups
constexpr int PITCHC   = 200;

constexpr int PST      = 68;                       // staging pitch (f32)
constexpr int ST_BYTES = 128 * PST * 4;            // 34816 (single buffer)
constexpr int AP_BYTES = 64 * 32 * 16;             // 32768: [fg=64][lane][16B]
constexpr int BP_BYTES = 3 * 8 * 4 * 32 * 16;      // 49152: [wc=3][kk=8][j=4][lane][16B]
constexpr int OFF_ST   = 0;
constexpr int OFF_AP   = ST_BYTES;                 // 34816, 2 bufs
constexpr int OFF_BP   = OFF_AP + 2 * AP_BYTES;    // 100352, 2 bufs
constexpr int SMEM_BYTES = OFF_BP + 2 * BP_BYTES;  // 198656
}

__device__ __forceinline__ uint32_t smem_u32(const void* p) {
    uint32_t a;
    asm("{ .reg .u64 t; cvta.to.shared.u64 t, %1; cvt.u32.u64 %0, t; }"
        : "=r"(a) : "l"(p));
    return a;
}
__device__ __forceinline__ uint32_t f2tf32(float x) {
    uint32_t r;
    asm("cvt.rna.tf32.f32 %0, %1;" : "=r"(r) : "f"(x));
    return r;
}
__device__ __forceinline__ void mma_tf32(float* c, const uint32_t* a,
                                         uint32_t b0, uint32_t b1) {
    asm("mma.sync.aligned.m16n8k8.row.col.f32.tf32.tf32.f32 "
        "{%0,%1,%2,%3}, {%4,%5,%6,%7}, {%8,%9}, {%0,%1,%2,%3};"
        : "+f"(c[0]), "+f"(c[1]), "+f"(c[2]), "+f"(c[3])
        : "r"(a[0]), "r"(a[1]), "r"(a[2]), "r"(a[3]), "r"(b0), "r"(b1));
}
__device__ __forceinline__ void cp16(uint32_t smem_dst, const void* gmem_src) {
    asm volatile("cp.async.cg.shared.global [%0], [%1], 16;"
                 :: "r"(smem_dst), "l"(gmem_src) : "memory");
}
__device__ __forceinline__ void cp_commit() {
    asm volatile("cp.async.commit_group;" ::: "memory");
}
__device__ __forceinline__ void cp_wait0() {
    asm volatile("cp.async.wait_group 0;" ::: "memory");
}

// ---- B: pre-rounded tf32, pre-permuted into fragment order (one-time) ------
// per slice: [wc=3][kk=8][j=4][lane=32][4 floats] = 12288 f32 = 48KB
__device__ __align__(16) float g_BP[NSLICES][12288];

__global__ void conv_w_kernel(const float* __restrict__ Wk,
                              const float* __restrict__ Wq,
                              const float* __restrict__ Wv) {
    int idx = blockIdx.x * 256 + threadIdx.x;   // 0..98303
    int s = idx / 12288;
    int r = idx % 12288;
    int pos  = r & 3;
    int lane = (r >> 2) & 31;
    int j    = (r >> 7) & 3;
    int kk   = (r >> 9) & 7;
    int wc   = r >> 12;                          // 0..2

    int f  = j * 4 + pos;        // 0..15
    int ng = f >> 1;             // 0..7
    int h  = f & 1;
    int n  = wc * 64 + ng * 8 + (lane >> 2);
    int k  = s * KT + kk * 8 + (lane & 3) + h * 4;

    const float* W = (n < 64) ? Wk : ((n < 128) ? Wq : Wv);
    float x = W[k * 64 + (n % 64)];
    g_BP[s][(((wc * 8 + kk) * 4 + j) * 32 + lane) * 4 + pos] =
        __uint_as_float(f2tf32(x));
}

// ---------------- main fused kernel ----------------
__global__ __launch_bounds__(THREADS, 1)
void attn_mma_kernel(const float* __restrict__ drug, float* __restrict__ out) {
    extern __shared__ __align__(128) char sm[];
    const uint32_t sb = smem_u32(sm);
    const int tid  = threadIdx.x;
    const int wid  = tid >> 5;
    const int lane = tid & 31;
    const int wr   = wid & 3;          // row group (32 rows)
    const int wc   = wid >> 2;         // col group (64 cols), 0..2
    const int R0   = wr * 32;
    const int C0   = wc * 64;
    const int row0 = blockIdx.x * 128;

    // ---- producers ----
    auto issue_Araw = [&](int s) {          // drug slice -> ST (raw f32, pitch 68)
        const float* src = drug + (size_t)row0 * F + s * KT;
        #pragma unroll
        for (int i = 0; i < 6; i++) {
            int idx = tid + i * THREADS;    // 16B chunks, 2048 total
            if (idx < 2048) {
                int r   = idx >> 4;
                int c16 = idx & 15;
                cp16(sb + OFF_ST + (uint32_t)(r * PST * 4 + c16 * 16),
                     src + (size_t)r * F + c16 * 4);
            }
        }
    };
    auto issue_BP = [&](int s, int buf) {   // permuted B slice -> BP[buf]
        uint32_t dst = sb + OFF_BP + buf * BP_BYTES;
        #pragma unroll
        for (int i = 0; i < 8; i++) {
            int idx = tid + i * THREADS;    // 0..3071 chunks
            cp16(dst + (uint32_t)idx * 16, &g_BP[s][idx * 4]);
        }
    };
    // convert ST (raw f32) -> AP[buf] (tf32 bits, fragment order)
    auto convert_A = [&](int abuf) {
        const float* stf = reinterpret_cast<const float*>(sm + OFF_ST);
        char* apb = sm + OFF_AP + abuf * AP_BYTES;
        #pragma unroll
        for (int i = 0; i < 6; i++) {
            int item = tid + i * THREADS;   // fg*32+lane, 2048 total
            if (item < 2048) {
                int fg  = item >> 5;
                int ln  = item & 31;
                int kkq = fg >> 3;
                int wrq = (fg >> 1) & 3;
                int rtq = fg & 1;
                int r1  = wrq * 32 + rtq * 16 + (ln >> 2);
                int c1  = kkq * 8 + (ln & 3);
                uint32_t a0 = f2tf32(stf[r1 * PST + c1]);
                uint32_t a1 = f2tf32(stf[(r1 + 8) * PST + c1]);
                uint32_t a2 = f2tf32(stf[r1 * PST + c1 + 4]);
                uint32_t a3 = f2tf32(stf[(r1 + 8) * PST + c1 + 4]);
                *reinterpret_cast<uint4*>(apb + (uint32_t)item * 16) =
                    make_uint4(a0, a1, a2, a3);
            }
        }
    };

    float acc[2][8][4];
    #pragma unroll
    for (int i = 0; i < 2; i++)
        #pragma unroll
        for (int j = 0; j < 8; j++)
            #pragma unroll
            for (int q = 0; q < 4; q++)
                acc[i][j][q] = 0.f;

    // ---- prologue ----
    issue_Araw(0);
    issue_BP(0, 0);
    cp_commit();
    cp_wait0();
    __syncthreads();
    convert_A(0);
    __syncthreads();
    issue_Araw(1);
    issue_BP(1, 1);
    cp_commit();

    // ---- main loop over K slices ----
    for (int s = 0; s < NSLICES; s++) {
        const int buf  = s & 1;
        const int nbuf = buf ^ 1;

        const char* apb = sm + OFF_AP + buf * AP_BYTES;
        const char* bpb = sm + OFF_BP + buf * BP_BYTES;

        // fragment registers, double-buffered over kk
        uint32_t afr[2][2][4];     // [parity][rt][4]
        uint32_t bfr[2][4][4];     // [parity][j][4]

        auto load_frags = [&](int kk, int par) {
            #pragma unroll
            for (int rt = 0; rt < 2; rt++) {
                int fg = (kk * 4 + wr) * 2 + rt;
                uint4 v = *reinterpret_cast<const uint4*>(
                    apb + (uint32_t)(fg * 32 + lane) * 16);
                afr[par][rt][0] = v.x; afr[par][rt][1] = v.y;
                afr[par][rt][2] = v.z; afr[par][rt][3] = v.w;
            }
            #pragma unroll
            for (int j = 0; j < 4; j++) {
                uint4 v = *reinterpret_cast<const uint4*>(
                    bpb + (uint32_t)(((wc * 8 + kk) * 4 + j) * 32 + lane) * 16);
                bfr[par][j][0] = v.x; bfr[par][j][1] = v.y;
                bfr[par][j][2] = v.z; bfr[par][j][3] = v.w;
            }
        };

        load_frags(0, 0);
        #pragma unroll
        for (int kk = 0; kk < 8; kk++) {
            const int cur = kk & 1;
            const int nxt = cur ^ 1;
            if (kk < 7) load_frags(kk + 1, nxt);   // prefetch under MMAs
            #pragma unroll
            for (int ng = 0; ng < 8; ng++) {
                uint32_t b0 = bfr[cur][ng >> 1][(2 * ng) & 3];
                uint32_t b1 = bfr[cur][ng >> 1][(2 * ng + 1) & 3];
                #pragma unroll
                for (int rt = 0; rt < 2; rt++)
                    mma_tf32(acc[rt][ng], afr[cur][rt], b0, b1);
            }
        }

        if (s + 1 < NSLICES) {
            cp_wait0();
            __syncthreads();
            convert_A(nbuf);
            __syncthreads();
            if (s + 2 < NSLICES) {
                issue_Araw(s + 2);
                issue_BP(s + 2, buf);
                cp_commit();
            }
        }
    }
    __syncthreads();

    // ---- park C [128 x 192] fp32 in smem (aliases pipeline buffers) ----
    float* Cs = reinterpret_cast<float*>(sm);
    {
        int cr = lane >> 2;
        int cc = 2 * (lane & 3);
        #pragma unroll
        for (int rt = 0; rt < 2; rt++) {
            #pragma unroll
            for (int nt = 0; nt < 8; nt++) {
                int r = R0 + rt * 16 + cr;
                int c = C0 + nt * 8 + cc;
                *reinterpret_cast<float2*>(&Cs[r * PITCHC + c]) =
                    make_float2(acc[rt][nt][0], acc[rt][nt][1]);
                *reinterpret_cast<float2*>(&Cs[(r + 8) * PITCHC + c]) =
                    make_float2(acc[rt][nt][2], acc[rt][nt][3]);
            }
        }
    }
    __syncthreads();

    // ---- attention epilogue: 8 threads per batch (threads 0..255) ----
    if (tid < 256) {
        const int bl    = tid >> 3;
        const int g     = tid & 7;
        const int rbase = bl * 4;

        float kf[4][8], qf[4][8], vf[4][8];
        #pragma unroll
        for (int n = 0; n < 4; n++) {
            const float* p = &Cs[(rbase + n) * PITCHC + g * 8];
            *(float4*)&kf[n][0] = *(const float4*)(p);
            *(float4*)&kf[n][4] = *(const float4*)(p + 4);
            *(float4*)&qf[n][0] = *(const float4*)(p + 64);
            *(float4*)&qf[n][4] = *(const float4*)(p + 68);
            *(float4*)&vf[n][0] = *(const float4*)(p + 128);
            *(float4*)&vf[n][4] = *(const float4*)(p + 132);
        }

        float sc[4][4];
        #pragma unroll
        for (int n = 0; n < 4; n++)
            #pragma unroll
            for (int m = 0; m < 4; m++) {
                float a = 0.f;
                #pragma unroll
                for (int dd = 0; dd < 8; dd++)
                    a = fmaf(kf[n][dd], qf[m][dd], a);
                sc[n][m] = a;
            }
        #pragma unroll
        for (int off = 4; off > 0; off >>= 1)
            #pragma unroll
            for (int n = 0; n < 4; n++)
                #pragma unroll
                for (int m = 0; m < 4; m++)
                    sc[n][m] += __shfl_xor_sync(0xffffffffu, sc[n][m], off);

        float res[8];
        #pragma unroll
        for (int dd = 0; dd < 8; dd++) res[dd] = -3.402823466e38f;

        #pragma unroll
        for (int n = 0; n < 4; n++) {
            float mx = fmaxf(fmaxf(sc[n][0], sc[n][1]), fmaxf(sc[n][2], sc[n][3]));
            float p[4];
            float sum = 0.f;
            #pragma unroll
            for (int m = 0; m < 4; m++) { p[m] = expf(sc[n][m] - mx); sum += p[m]; }
            float inv = 1.f / sum;
            #pragma unroll
            for (int dd = 0; dd < 8; dd++) {
                float o = 0.f;
                #pragma unroll
                for (int m = 0; m < 4; m++)
                    o = fmaf(p[m] * inv, vf[m][dd], o);
                res[dd] = fmaxf(res[dd], o);
            }
        }

        const int b = blockIdx.x * 32 + bl;
        float* op = &out[(size_t)b * 64 + g * 8];
        *(float4*)op       = make_float4(res[0], res[1], res[2], res[3]);
        *(float4*)(op + 4) = make_float4(res[4], res[5], res[6], res[7]);
    }
}

// ---------------- launch ----------------
extern "C" void kernel_launch(void* const* d_in, const int* in_sizes, int n_in,
                              void* d_out, int out_size) {
    const float* drug = (const float*)d_in[0];
    const float* Wk   = (const float*)d_in[1];
    const float* Wq   = (const float*)d_in[2];
    const float* Wv   = (const float*)d_in[3];
    float* out        = (float*)d_out;

    conv_w_kernel<<<98304 / 256, 256>>>(Wk, Wq, Wv);

    cudaFuncSetAttribute(attn_mma_kernel,
                         cudaFuncAttributeMaxDynamicSharedMemorySize, SMEM_BYTES);
    attn_mma_kernel<<<1024, THREADS, SMEM_BYTES>>>(drug, out);
}

// round 10
// speedup vs baseline: 1.1171x; 1.1171x over previous
#include <cuda_runtime.h>
#include <cuda_bf16.h>
#include <cstdint>

// ============================================================================
// drug[32768,4,512] f32, Wk/Wq/Wv[512,64] f32 -> out[32768,64] f32
// out[b] = max_n softmax_m( (X Wk)(X Wq)^T )[n,:] @ (X Wv),  X = drug[b] (4x512)
//
// R10: 2 CTAs/SM. CTA tile 64x192 (16 batches), 2048 CTAs, 256 threads
// (8 warps, 2 row x 4 col groups). tf32 m16n8k8 single-pass. Smem 98KB/CTA
// (ST x2 + AP + BP). Cross-CTA overlap hides load/convert/barrier bubbles.
// ============================================================================

namespace {
constexpr int F        = 512;
constexpr int KT       = 64;
constexpr int NSLICES  = F / KT;      // 8
constexpr int MROWS    = 64;          // rows per CTA (16 batches)
constexpr int THREADS  = 256;         // 8 warps: wr(2) x wc(4)
constexpr int PITCHC   = 200;

constexpr int PST      = 68;
constexpr int ST_BYTES = MROWS * PST * 4;          // 17408 per buf (x2)
constexpr int AP_BYTES = 32 * 32 * 16;             // 16384: [fg=32][lane][16B]
constexpr int BP_BYTES = 4 * 8 * 3 * 32 * 16;      // 49152: [wc4][kk8][j3][lane][16B]
constexpr int OFF_ST   = 0;
constexpr int OFF_AP   = 2 * ST_BYTES;             // 34816
constexpr int OFF_BP   = OFF_AP + AP_BYTES;        // 51200
constexpr int SMEM_BYTES = OFF_BP + BP_BYTES;      // 100352 (98KB)
}

__device__ __forceinline__ uint32_t smem_u32(const void* p) {
    uint32_t a;
    asm("{ .reg .u64 t; cvta.to.shared.u64 t, %1; cvt.u32.u64 %0, t; }"
        : "=r"(a) : "l"(p));
    return a;
}
__device__ __forceinline__ uint32_t f2tf32(float x) {
    uint32_t r;
    asm("cvt.rna.tf32.f32 %0, %1;" : "=r"(r) : "f"(x));
    return r;
}
__device__ __forceinline__ void mma_tf32(float* c, const uint32_t* a,
                                         uint32_t b0, uint32_t b1) {
    asm("mma.sync.aligned.m16n8k8.row.col.f32.tf32.tf32.f32 "
        "{%0,%1,%2,%3}, {%4,%5,%6,%7}, {%8,%9}, {%0,%1,%2,%3};"
        : "+f"(c[0]), "+f"(c[1]), "+f"(c[2]), "+f"(c[3])
        : "r"(a[0]), "r"(a[1]), "r"(a[2]), "r"(a[3]), "r"(b0), "r"(b1));
}
__device__ __forceinline__ void cp16(uint32_t smem_dst, const void* gmem_src) {
    asm volatile("cp.async.cg.shared.global [%0], [%1], 16;"
                 :: "r"(smem_dst), "l"(gmem_src) : "memory");
}
__device__ __forceinline__ void cp_commit() {
    asm volatile("cp.async.commit_group;" ::: "memory");
}
template <int N>
__device__ __forceinline__ void cp_wait() {
    asm volatile("cp.async.wait_group %0;" :: "n"(N) : "memory");
}

// ---- B: pre-rounded tf32, fragment order (one-time prepass; same as R8) ----
// per slice: [wc=4][kk=8][j=3][lane=32][4 floats] = 12288 f32 = 48KB
__device__ __align__(16) float g_BP[NSLICES][12288];

__global__ void conv_w_kernel(const float* __restrict__ Wk,
                              const float* __restrict__ Wq,
                              const float* __restrict__ Wv) {
    int idx = blockIdx.x * 256 + threadIdx.x;   // 0..98303
    int pos  = idx & 3;
    int lane = (idx >> 2) & 31;
    int j    = (idx >> 7) % 3;
    int kk   = (idx / (3 * 128)) & 7;
    int wc   = (idx / (3 * 128 * 8)) & 3;
    int s    = idx / (3 * 128 * 8 * 4);

    int f  = j * 4 + pos;        // 0..11
    int ng = f >> 1;             // 0..5
    int h  = f & 1;
    int n  = wc * 48 + ng * 8 + (lane >> 2);
    int k  = s * KT + kk * 8 + (lane & 3) + h * 4;

    const float* W = (n < 64) ? Wk : ((n < 128) ? Wq : Wv);
    float x = W[k * 64 + (n % 64)];
    g_BP[s][(((wc * 8 + kk) * 3 + j) * 32 + lane) * 4 + pos] =
        __uint_as_float(f2tf32(x));
}

// ---------------- main fused kernel ----------------
__global__ __launch_bounds__(THREADS, 2)
void attn_mma_kernel(const float* __restrict__ drug, float* __restrict__ out) {
    extern __shared__ __align__(128) char sm[];
    const uint32_t sb = smem_u32(sm);
    const int tid  = threadIdx.x;
    const int wid  = tid >> 5;
    const int lane = tid & 31;
    const int wr   = wid & 1;          // 2 row groups (32 rows)
    const int wc   = wid >> 1;         // 4 col groups (48 cols)
    const int R0   = wr * 32;
    const int C0   = wc * 48;
    const int row0 = blockIdx.x * MROWS;

    // ---- producers (256 threads) ----
    auto issue_A = [&](int s, int par) {     // drug slice -> ST[par], raw f32
        uint32_t dst = sb + OFF_ST + par * ST_BYTES;
        const float* src = drug + (size_t)row0 * F + s * KT;
        #pragma unroll
        for (int i = 0; i < 4; i++) {
            int idx = tid + i * THREADS;     // 0..1023 (64 rows x 16 chunks)
            int r   = idx >> 4;
            int c16 = idx & 15;
            cp16(dst + (uint32_t)(r * PST * 4 + c16 * 16),
                 src + (size_t)r * F + c16 * 4);
        }
    };
    auto issue_B = [&](int s) {              // permuted B slice -> BP
        #pragma unroll
        for (int i = 0; i < 12; i++) {
            int idx = tid + i * THREADS;     // 0..3071 chunks
            cp16(sb + OFF_BP + (uint32_t)idx * 16, &g_BP[s][idx * 4]);
        }
    };
    // ST[par] (raw f32) -> AP (tf32 bits, fragment order). fg = (kk*2+wr)*2+rt
    auto convert_A = [&](int par) {
        const float* stf = reinterpret_cast<const float*>(sm + OFF_ST + par * ST_BYTES);
        char* apb = sm + OFF_AP;
        #pragma unroll
        for (int i = 0; i < 4; i++) {
            int item = tid + i * THREADS;    // 0..1023 (32 fg x 32 lanes)
            int fg  = item >> 5;
            int ln  = item & 31;
            int kkq = fg >> 2;
            int wrq = (fg >> 1) & 1;
            int rtq = fg & 1;
            int r1  = wrq * 32 + rtq * 16 + (ln >> 2);
            int c1  = kkq * 8 + (ln & 3);
            uint32_t a0 = f2tf32(stf[r1 * PST + c1]);
            uint32_t a1 = f2tf32(stf[(r1 + 8) * PST + c1]);
            uint32_t a2 = f2tf32(stf[r1 * PST + c1 + 4]);
            uint32_t a3 = f2tf32(stf[(r1 + 8) * PST + c1 + 4]);
            *reinterpret_cast<uint4*>(apb + (uint32_t)item * 16) =
                make_uint4(a0, a1, a2, a3);
        }
    };

    float acc[2][6][4];
    #pragma unroll
    for (int i = 0; i < 2; i++)
        #pragma unroll
        for (int j = 0; j < 6; j++)
            #pragma unroll
            for (int q = 0; q < 4; q++)
                acc[i][j][q] = 0.f;

    // ---- prologue ----
    issue_A(0, 0); cp_commit();      // GA0
    issue_B(0);    cp_commit();      // GB0
    issue_A(1, 1); cp_commit();      // GA1
    cp_wait<1>();                    // GA0, GB0 done (GA1 may fly)
    __syncthreads();
    convert_A(0);                    // AP <- slice 0
    __syncthreads();

    // ---- main loop over K slices ----
    for (int s = 0; s < NSLICES; s++) {
        const char* apb = sm + OFF_AP;
        const char* bpb = sm + OFF_BP;

        // prefetch A(s+2) into the ST buffer freed by convert_A(s)
        if (s + 2 < NSLICES) { issue_A(s + 2, s & 1); cp_commit(); }

        #pragma unroll
        for (int kk = 0; kk < 8; kk++) {
            uint32_t a[2][4];
            #pragma unroll
            for (int rt = 0; rt < 2; rt++) {
                int fg = (kk * 2 + wr) * 2 + rt;
                uint4 v = *reinterpret_cast<const uint4*>(
                    apb + (uint32_t)(fg * 32 + lane) * 16);
                a[rt][0] = v.x; a[rt][1] = v.y; a[rt][2] = v.z; a[rt][3] = v.w;
            }
            uint32_t b[12];
            #pragma unroll
            for (int j = 0; j < 3; j++) {
                uint4 v = *reinterpret_cast<const uint4*>(
                    bpb + (uint32_t)(((wc * 8 + kk) * 3 + j) * 32 + lane) * 16);
                b[4 * j]     = v.x;
                b[4 * j + 1] = v.y;
                b[4 * j + 2] = v.z;
                b[4 * j + 3] = v.w;
            }
            #pragma unroll
            for (int ng = 0; ng < 6; ng++)
                #pragma unroll
                for (int rt = 0; rt < 2; rt++)
                    mma_tf32(acc[rt][ng], a[rt], b[2 * ng], b[2 * ng + 1]);
        }

        __syncthreads();                       // AP + BP free
        if (s + 1 < NSLICES) {
            issue_B(s + 1); cp_commit();       // GB(s+1) -> BP
            convert_A((s + 1) & 1);            // AP <- slice s+1 (GA(s+1) done: see waits)
            // ensure GB(s+1) landed (leave GA(s+3)-to-be and GA(s+2) pending rules):
            if (s + 3 < NSLICES) cp_wait<1>(); // all but GA(s+2) done -> GB(s+1) done? no:
                                               // order: GA(s+2), GB(s+1) -> newest is GB(s+1).
            // NOTE: must wait so that GB(s+1) is complete before next MMA.
            if (s + 3 < NSLICES) { /* handled below */ } 
            cp_wait<0>();                      // conservative: all in-flight done
            __syncthreads();
        }
    }
    __syncthreads();

    // ---- park C [64 x 192] fp32 in smem (aliases pipeline buffers) ----
    float* Cs = reinterpret_cast<float*>(sm);
    {
        int cr = lane >> 2;
        int cc = 2 * (lane & 3);
        #pragma unroll
        for (int rt = 0; rt < 2; rt++) {
            #pragma unroll
            for (int nt = 0; nt < 6; nt++) {
                int r = R0 + rt * 16 + cr;
                int c = C0 + nt * 8 + cc;
                *reinterpret_cast<float2*>(&Cs[r * PITCHC + c]) =
                    make_float2(acc[rt][nt][0], acc[rt][nt][1]);
                *reinterpret_cast<float2*>(&Cs[(r + 8) * PITCHC + c]) =
                    make_float2(acc[rt][nt][2], acc[rt][nt][3]);
            }
        }
    }
    __syncthreads();

    // ---- attention epilogue: 8 threads per batch (threads 0..127) ----
    if (tid < 128) {
        const int bl    = tid >> 3;        // 0..15
        const int g     = tid & 7;
        const int rbase = bl * 4;

        float kf[4][8], qf[4][8], vf[4][8];
        #pragma unroll
        for (int n = 0; n < 4; n++) {
            const float* p = &Cs[(rbase + n) * PITCHC + g * 8];
            *(float4*)&kf[n][0] = *(const float4*)(p);
            *(float4*)&kf[n][4] = *(const float4*)(p + 4);
            *(float4*)&qf[n][0] = *(const float4*)(p + 64);
            *(float4*)&qf[n][4] = *(const float4*)(p + 68);
            *(float4*)&vf[n][0] = *(const float4*)(p + 128);
            *(float4*)&vf[n][4] = *(const float4*)(p + 132);
        }

        float sc[4][4];
        #pragma unroll
        for (int n = 0; n < 4; n++)
            #pragma unroll
            for (int m = 0; m < 4; m++) {
                float a = 0.f;
                #pragma unroll
                for (int dd = 0; dd < 8; dd++)
                    a = fmaf(kf[n][dd], qf[m][dd], a);
                sc[n][m] = a;
            }
        #pragma unroll
        for (int off = 4; off > 0; off >>= 1)
            #pragma unroll
            for (int n = 0; n < 4; n++)
                #pragma unroll
                for (int m = 0; m < 4; m++)
                    sc[n][m] += __shfl_xor_sync(0xffffffffu, sc[n][m], off);

        float res[8];
        #pragma unroll
        for (int dd = 0; dd < 8; dd++) res[dd] = -3.402823466e38f;

        #pragma unroll
        for (int n = 0; n < 4; n++) {
            float mx = fmaxf(fmaxf(sc[n][0], sc[n][1]), fmaxf(sc[n][2], sc[n][3]));
            float p[4];
            float sum = 0.f;
            #pragma unroll
            for (int m = 0; m < 4; m++) { p[m] = expf(sc[n][m] - mx); sum += p[m]; }
            float inv = 1.f / sum;
            #pragma unroll
            for (int dd = 0; dd < 8; dd++) {
                float o = 0.f;
                #pragma unroll
                for (int m = 0; m < 4; m++)
                    o = fmaf(p[m] * inv, vf[m][dd], o);
                res[dd] = fmaxf(res[dd], o);
            }
        }

        const int b = blockIdx.x * 16 + bl;
        float* op = &out[(size_t)b * 64 + g * 8];
        *(float4*)op       = make_float4(res[0], res[1], res[2], res[3]);
        *(float4*)(op + 4) = make_float4(res[4], res[5], res[6], res[7]);
    }
}

// ---------------- launch ----------------
extern "C" void kernel_launch(void* const* d_in, const int* in_sizes, int n_in,
                              void* d_out, int out_size) {
    const float* drug = (const float*)d_in[0];
    const float* Wk   = (const float*)d_in[1];
    const float* Wq   = (const float*)d_in[2];
    const float* Wv   = (const float*)d_in[3];
    float* out        = (float*)d_out;

    conv_w_kernel<<<98304 / 256, 256>>>(Wk, Wq, Wv);

    cudaFuncSetAttribute(attn_mma_kernel,
                         cudaFuncAttributeMaxDynamicSharedMemorySize, SMEM_BYTES);
    attn_mma_kernel<<<2048, THREADS, SMEM_BYTES>>>(drug, out);
}

// round 11
// speedup vs baseline: 1.6892x; 1.5121x over previous
#include <cuda_runtime.h>
#include <cuda_fp16.h>
#include <cstdint>

// ============================================================================
// drug[32768,4,512] f32, Wk/Wq/Wv[512,64] f32 -> out[32768,64] f32
// out[b] = max_n softmax_m( (X Wk)(X Wq)^T )[n,:] @ (X Wv),  X = drug[b] (4x512)
//
// R11: fp16 single-pass mma.m16n8k16 (11-bit mantissa == tf32 precision, but
// 2x K per instruction -> tensor floor halves to ~42us). 2 CTAs/SM, CTA tile
// 64x192 (16 batches), 256 threads (8 warps, 2 row x 4 col groups).
// Fragment-order smem: B pre-permuted fp16 in prepass; A staged f32 then
// converted to fp16 fragments once per slice. AP/BP/ST double-buffered.
// ============================================================================

namespace {
constexpr int F        = 512;
constexpr int KT       = 64;
constexpr int NSLICES  = F / KT;      // 8
constexpr int MROWS    = 64;          // rows per CTA (16 batches)
constexpr int THREADS  = 256;         // 8 warps: wr(2) x wc(4)
constexpr int PITCHC   = 200;

constexpr int PST      = 68;
constexpr int ST_BYTES = MROWS * PST * 4;          // 17408 per buf (x2)
constexpr int AP_BYTES = 16 * 32 * 16;             // 8192: [fg=16][lane][16B] (x2)
constexpr int BP_BYTES = 4 * 4 * 3 * 32 * 16;      // 24576: [wc4][kt4][j3][lane][16B] (x2)
constexpr int OFF_ST   = 0;                        // 2 x 17408
constexpr int OFF_AP   = 2 * ST_BYTES;             // 34816, 2 x 8192
constexpr int OFF_BP   = OFF_AP + 2 * AP_BYTES;    // 51200, 2 x 24576
constexpr int SMEM_BYTES = OFF_BP + 2 * BP_BYTES;  // 100352 (98KB) -> 2 CTAs/SM
}

__device__ __forceinline__ uint32_t smem_u32(const void* p) {
    uint32_t a;
    asm("{ .reg .u64 t; cvta.to.shared.u64 t, %1; cvt.u32.u64 %0, t; }"
        : "=r"(a) : "l"(p));
    return a;
}
__device__ __forceinline__ uint32_t pack_h2(float lo, float hi) {
    __half l = __float2half_rn(lo), h = __float2half_rn(hi);
    return (uint32_t)__half_as_ushort(l) | ((uint32_t)__half_as_ushort(h) << 16);
}
__device__ __forceinline__ void mma_f16(float* c, const uint32_t* a,
                                        uint32_t b0, uint32_t b1) {
    asm("mma.sync.aligned.m16n8k16.row.col.f32.f16.f16.f32 "
        "{%0,%1,%2,%3}, {%4,%5,%6,%7}, {%8,%9}, {%0,%1,%2,%3};"
        : "+f"(c[0]), "+f"(c[1]), "+f"(c[2]), "+f"(c[3])
        : "r"(a[0]), "r"(a[1]), "r"(a[2]), "r"(a[3]), "r"(b0), "r"(b1));
}
__device__ __forceinline__ void cp16(uint32_t smem_dst, const void* gmem_src) {
    asm volatile("cp.async.cg.shared.global [%0], [%1], 16;"
                 :: "r"(smem_dst), "l"(gmem_src) : "memory");
}
__device__ __forceinline__ void cp_commit() {
    asm volatile("cp.async.commit_group;" ::: "memory");
}
template <int N>
__device__ __forceinline__ void cp_wait() {
    asm volatile("cp.async.wait_group %0;" :: "n"(N) : "memory");
}

// ---- B: fp16, fragment order (one-time prepass) -----------------------------
// per slice: [wc=4][kt=4][j=3][lane=32][pos=4] uint32 (2 fp16 each) = 24KB
// reg f = j*4+pos in 0..11: ng = f>>1 (0..5), h = f&1 (b0/b1)
//   n = wc*48 + ng*8 + (lane>>2)
//   k = s*64 + kt*16 + (lane&3)*2 + h*8 ; pack {W[k][n], W[k+1][n]}
__device__ __align__(16) uint32_t g_BP[NSLICES][6144];

__global__ void conv_w_kernel(const float* __restrict__ Wk,
                              const float* __restrict__ Wq,
                              const float* __restrict__ Wv) {
    int idx = blockIdx.x * 256 + threadIdx.x;   // 0..49151
    int pos  = idx & 3;
    int lane = (idx >> 2) & 31;
    int j    = (idx >> 7) % 3;
    int kt   = (idx / 384) & 3;
    int wc   = (idx / 1536) & 3;
    int s    = idx / 6144;

    int f  = j * 4 + pos;
    int ng = f >> 1;
    int h  = f & 1;
    int n  = wc * 48 + ng * 8 + (lane >> 2);
    int k  = s * KT + kt * 16 + (lane & 3) * 2 + h * 8;

    const float* W = (n < 64) ? Wk : ((n < 128) ? Wq : Wv);
    int col = n % 64;
    float lo = W[k * 64 + col];
    float hi = W[(k + 1) * 64 + col];
    g_BP[s][(((wc * 4 + kt) * 3 + j) * 32 + lane) * 4 + pos] = pack_h2(lo, hi);
}

// ---------------- main fused kernel ----------------
__global__ __launch_bounds__(THREADS, 2)
void attn_mma_kernel(const float* __restrict__ drug, float* __restrict__ out) {
    extern __shared__ __align__(128) char sm[];
    const uint32_t sb = smem_u32(sm);
    const int tid  = threadIdx.x;
    const int wid  = tid >> 5;
    const int lane = tid & 31;
    const int wr   = wid & 1;          // 2 row groups (32 rows)
    const int wc   = wid >> 1;         // 4 col groups (48 cols)
    const int R0   = wr * 32;
    const int C0   = wc * 48;
    const int row0 = blockIdx.x * MROWS;

    // ---- producers ----
    auto issue_A = [&](int s, int par) {     // drug slice -> ST[par], raw f32
        uint32_t dst = sb + OFF_ST + par * ST_BYTES;
        const float* src = drug + (size_t)row0 * F + s * KT;
        #pragma unroll
        for (int i = 0; i < 4; i++) {
            int idx = tid + i * THREADS;     // 0..1023 (64 rows x 16 chunks)
            int r   = idx >> 4;
            int c16 = idx & 15;
            cp16(dst + (uint32_t)(r * PST * 4 + c16 * 16),
                 src + (size_t)r * F + c16 * 4);
        }
    };
    auto issue_B = [&](int s, int buf) {     // permuted B slice -> BP[buf]
        uint32_t dst = sb + OFF_BP + buf * BP_BYTES;
        #pragma unroll
        for (int i = 0; i < 6; i++) {
            int idx = tid + i * THREADS;     // 0..1535 chunks of 16B
            cp16(dst + (uint32_t)idx * 16, &g_BP[s][idx * 4]);
        }
    };
    // ST[par] f32 -> AP[abuf] fp16 fragments. fg = kt*4 + wr*2 + rt (16 fgs)
    // item regs: a0=(r1,c..c+1) a1=(r1+8,c..) a2=(r1,c+8..) a3=(r1+8,c+8..)
    auto convert_A = [&](int par, int abuf) {
        const float* stf = reinterpret_cast<const float*>(sm + OFF_ST + par * ST_BYTES);
        char* apb = sm + OFF_AP + abuf * AP_BYTES;
        #pragma unroll
        for (int i = 0; i < 2; i++) {
            int item = tid + i * THREADS;    // 0..511 (16 fg x 32 lanes)
            int fg  = item >> 5;
            int ln  = item & 31;
            int kt  = fg >> 2;
            int wrq = (fg >> 1) & 1;
            int rtq = fg & 1;
            int r1  = wrq * 32 + rtq * 16 + (ln >> 2);
            int c   = kt * 16 + (ln & 3) * 2;
            const float* p0 = &stf[r1 * PST + c];
            const float* p1 = &stf[(r1 + 8) * PST + c];
            uint32_t a0 = pack_h2(p0[0], p0[1]);
            uint32_t a1 = pack_h2(p1[0], p1[1]);
            uint32_t a2 = pack_h2(p0[8], p0[9]);
            uint32_t a3 = pack_h2(p1[8], p1[9]);
            *reinterpret_cast<uint4*>(apb + (uint32_t)item * 16) =
                make_uint4(a0, a1, a2, a3);
        }
    };

    float acc[2][6][4];
    #pragma unroll
    for (int i = 0; i < 2; i++)
        #pragma unroll
        for (int j = 0; j < 6; j++)
            #pragma unroll
            for (int q = 0; q < 4; q++)
                acc[i][j][q] = 0.f;

    // ---- prologue ----
    issue_A(0, 0); issue_B(0, 0); cp_commit();   // G(A0,B0)
    issue_A(1, 1); cp_commit();                  // G(A1)
    cp_wait<1>();                                // A0,B0 done; A1 flying
    __syncthreads();
    convert_A(0, 0);                             // AP[0] <- slice 0
    __syncthreads();

    // ---- main loop over K slices ----
    // invariant at top of iter s: pending groups = { A(s+1) }
    for (int s = 0; s < NSLICES; s++) {
        const int buf  = s & 1;
        const int nbuf = buf ^ 1;

        if (s + 1 < NSLICES) { issue_B(s + 1, nbuf); cp_commit(); }
        if (s + 2 < NSLICES) { issue_A(s + 2, s & 1); cp_commit(); }

        const char* apb = sm + OFF_AP + buf * AP_BYTES;
        const char* bpb = sm + OFF_BP + buf * BP_BYTES;

        #pragma unroll
        for (int kt = 0; kt < 4; kt++) {
            uint32_t a[2][4];
            #pragma unroll
            for (int rt = 0; rt < 2; rt++) {
                int fg = kt * 4 + wr * 2 + rt;
                uint4 v = *reinterpret_cast<const uint4*>(
                    apb + (uint32_t)(fg * 32 + lane) * 16);
                a[rt][0] = v.x; a[rt][1] = v.y; a[rt][2] = v.z; a[rt][3] = v.w;
            }
            uint32_t b[12];
            #pragma unroll
            for (int j = 0; j < 3; j++) {
                uint4 v = *reinterpret_cast<const uint4*>(
                    bpb + (uint32_t)(((wc * 4 + kt) * 3 + j) * 32 + lane) * 16);
                b[4 * j]     = v.x;
                b[4 * j + 1] = v.y;
                b[4 * j + 2] = v.z;
                b[4 * j + 3] = v.w;
            }
            #pragma unroll
            for (int ng = 0; ng < 6; ng++)
                #pragma unroll
                for (int rt = 0; rt < 2; rt++)
                    mma_f16(acc[rt][ng], a[rt], b[2 * ng], b[2 * ng + 1]);
        }

        if (s + 1 < NSLICES) {
            // need A(s+1) + B(s+1) landed; allow A(s+2) to keep flying
            if (s + 2 < NSLICES) cp_wait<1>(); else cp_wait<0>();
            __syncthreads();
            convert_A((s + 1) & 1, nbuf);       // AP[nbuf] <- slice s+1
            __syncthreads();
        }
    }
    __syncthreads();

    // ---- park C [64 x 192] fp32 in smem (aliases pipeline buffers) ----
    float* Cs = reinterpret_cast<float*>(sm);
    {
        int cr = lane >> 2;
        int cc = 2 * (lane & 3);
        #pragma unroll
        for (int rt = 0; rt < 2; rt++) {
            #pragma unroll
            for (int nt = 0; nt < 6; nt++) {
                int r = R0 + rt * 16 + cr;
                int c = C0 + nt * 8 + cc;
                *reinterpret_cast<float2*>(&Cs[r * PITCHC + c]) =
                    make_float2(acc[rt][nt][0], acc[rt][nt][1]);
                *reinterpret_cast<float2*>(&Cs[(r + 8) * PITCHC + c]) =
                    make_float2(acc[rt][nt][2], acc[rt][nt][3]);
            }
        }
    }
    __syncthreads();

    // ---- attention epilogue: 8 threads per batch (threads 0..127) ----
    if (tid < 128) {
        const int bl    = tid >> 3;        // 0..15
        const int g     = tid & 7;
        const int rbase = bl * 4;

        float kf[4][8], qf[4][8], vf[4][8];
        #pragma unroll
        for (int n = 0; n < 4; n++) {
            const float* p = &Cs[(rbase + n) * PITCHC + g * 8];
            *(float4*)&kf[n][0] = *(const float4*)(p);
            *(float4*)&kf[n][4] = *(const float4*)(p + 4);
            *(float4*)&qf[n][0] = *(const float4*)(p + 64);
            *(float4*)&qf[n][4] = *(const float4*)(p + 68);
            *(float4*)&vf[n][0] = *(const float4*)(p + 128);
            *(float4*)&vf[n][4] = *(const float4*)(p + 132);
        }

        float sc[4][4];
        #pragma unroll
        for (int n = 0; n < 4; n++)
            #pragma unroll
            for (int m = 0; m < 4; m++) {
                float a = 0.f;
                #pragma unroll
                for (int dd = 0; dd < 8; dd++)
                    a = fmaf(kf[n][dd], qf[m][dd], a);
                sc[n][m] = a;
            }
        #pragma unroll
        for (int off = 4; off > 0; off >>= 1)
            #pragma unroll
            for (int n = 0; n < 4; n++)
                #pragma unroll
                for (int m = 0; m < 4; m++)
                    sc[n][m] += __shfl_xor_sync(0xffffffffu, sc[n][m], off);

        float res[8];
        #pragma unroll
        for (int dd = 0; dd < 8; dd++) res[dd] = -3.402823466e38f;

        #pragma unroll
        for (int n = 0; n < 4; n++) {
            float mx = fmaxf(fmaxf(sc[n][0], sc[n][1]), fmaxf(sc[n][2], sc[n][3]));
            float p[4];
            float sum = 0.f;
            #pragma unroll
            for (int m = 0; m < 4; m++) { p[m] = expf(sc[n][m] - mx); sum += p[m]; }
            float inv = 1.f / sum;
            #pragma unroll
            for (int dd = 0; dd < 8; dd++) {
                float o = 0.f;
                #pragma unroll
                for (int m = 0; m < 4; m++)
                    o = fmaf(p[m] * inv, vf[m][dd], o);
                res[dd] = fmaxf(res[dd], o);
            }
        }

        const int b = blockIdx.x * 16 + bl;
        float* op = &out[(size_t)b * 64 + g * 8];
        *(float4*)op       = make_float4(res[0], res[1], res[2], res[3]);
        *(float4*)(op + 4) = make_float4(res[4], res[5], res[6], res[7]);
    }
}

// ---------------- launch ----------------
extern "C" void kernel_launch(void* const* d_in, const int* in_sizes, int n_in,
                              void* d_out, int out_size) {
    const float* drug = (const float*)d_in[0];
    const float* Wk   = (const float*)d_in[1];
    const float* Wq   = (const float*)d_in[2];
    const float* Wv   = (const float*)d_in[3];
    float* out        = (float*)d_out;

    conv_w_kernel<<<49152 / 256, 256>>>(Wk, Wq, Wv);

    cudaFuncSetAttribute(attn_mma_kernel,
                         cudaFuncAttributeMaxDynamicSharedMemorySize, SMEM_BYTES);
    attn_mma_kernel<<<2048, THREADS, SMEM_BYTES>>>(drug, out);
}